// round 13
// baseline (speedup 1.0000x reference)
#include <cuda_runtime.h>

// Fixed problem shape
#define NB 8
#define IC 16
#define OC 32
#define H  128
#define W  128
#define HP 130
#define TH 2      // output rows per CTA
#define TW 64     // output cols per CTA

typedef unsigned long long ull;

// Coefficient table: [j][i][k(padded to 4)] = (cos(theta[i*j,k]), -sin(theta[i*j,k]))
__device__ float2 g_coef[IC * OC * 4];          // 16 KB

// Packed (cos S, sin S): [n*IC][HP][W], 17 MB
__device__ ull g_cs[NB * IC * HP * W];

__device__ __forceinline__ void ffma2(ull& d, ull a, ull b) {
    asm("fma.rn.f32x2 %0, %1, %2, %0;" : "+l"(d) : "l"(a), "l"(b));
}

__device__ __forceinline__ ull pack2(float lo, float hi) {
    return (ull)__float_as_uint(lo) | ((ull)__float_as_uint(hi) << 32);
}

// ---------------- Kernel 1: coef table + cs tensor (proven) ----------------
#define CS_BLOCKS (NB * IC * HP * W / 256)      // 8320

__global__ __launch_bounds__(256)
void prep_kernel(const float* __restrict__ x, const float* __restrict__ theta) {
    if (blockIdx.x < 8) {
        int t = blockIdx.x * 256 + threadIdx.x;    // < 2048
        int j = t >> 7;
        int i = (t >> 2) & 31;
        int k = t & 3;
        float2 v = make_float2(0.f, 0.f);
        if (k < 3) {
            float th = theta[(i * j) * 3 + k];
            float s, c;
            sincosf(th, &s, &c);
            v = make_float2(c, -s);
        }
        g_coef[t] = v;
        return;
    }

    int idx  = (blockIdx.x - 8) * 256 + threadIdx.x;
    int w    = idx & 127;
    int rowi = idx >> 7;
    int hp   = rowi % HP;
    int nj   = rowi / HP;
    int lane = threadIdx.x & 31;

    ull outv;
    int gr = hp - 1;
    if ((unsigned)gr < (unsigned)H) {
        const float* xr = x + ((size_t)nj * H + gr) * W;
        float v  = xr[w];
        float vm = __shfl_up_sync(0xffffffffu, v, 1);
        if (lane == 0)  vm = (w > 0)   ? xr[w - 1] : 0.f;
        float vp = __shfl_down_sync(0xffffffffu, v, 1);
        if (lane == 31) vp = (w < 127) ? xr[w + 1] : 0.f;
        float S = vm + v + vp;
        float s, c;
        __sincosf(S, &s, &c);
        outv = pack2(c, s);
    } else {
        outv = pack2(1.f, 0.f);   // S = 0 on pad rows
    }
    g_cs[idx] = outv;
}

// ---------------- Kernel 2: contraction, 2x64 tile, occ 3, j-pipelined -----
// grid (2, 64, 8) = 1024 CTAs. 8 warps; warp ig owns channels 4*ig..4*ig+3.
// Thread owns cols {2*lane, 2*lane+1}, rows {h0, h0+1}; CS rows h0..h0+3.
// Double-buffered e-tile: j+1's 4 LDS.128 issue BEFORE j's FFMA burst,
// hiding LDS latency under >=96 cycles of FMA-pipe work.
__global__ __launch_bounds__(256, 3)
void contract_kernel(float* __restrict__ out) {
    __shared__ __align__(16) ull sCS[IC * (TH + 2) * TW];  // 32 KB
    __shared__ float2 sCoef[IC * OC * 4];                  // 16 KB

    const int tid  = threadIdx.x;
    const int lane = tid & 31;
    const int ig   = tid >> 5;
    const int tw   = blockIdx.x;
    const int h0   = blockIdx.y * TH;
    const int n    = blockIdx.z;

    // Stage coef table (1024 float4, 4 per thread)
    {
        const float4* src = reinterpret_cast<const float4*>(g_coef);
        float4* dst = reinterpret_cast<float4*>(sCoef);
        #pragma unroll
        for (int r = 0; r < 4; ++r)
            dst[tid + 256 * r] = src[tid + 256 * r];
    }

    // Stage CS slab: 16 j x 4 rows x 64 cols = 2048 ulonglong2 (8/thread)
    {
        const ull* gsrc = g_cs + ((size_t)n * IC * HP + h0) * W + tw * TW;
        #pragma unroll
        for (int it = 0; it < 8; ++it) {
            int q   = it * 256 + tid;     // 0..2047
            int c2  = q & 31;             // ulonglong2 within row
            int row = q >> 5;             // 0..63
            int r   = row & 3;
            int j   = row >> 2;
            ulonglong2 v = *reinterpret_cast<const ulonglong2*>(
                gsrc + ((size_t)j * HP + r) * W + 2 * c2);
            *reinterpret_cast<ulonglong2*>(sCS + (j * 4 + r) * TW + 2 * c2) = v;
        }
    }
    __syncthreads();   // the only barrier

    // acc[q][i][r]: q = col-in-pair, i = channel, r = output row
    ull acc[2][4][2];
    #pragma unroll
    for (int q = 0; q < 2; ++q)
        #pragma unroll
        for (int i = 0; i < 4; ++i) {
            acc[q][i][0] = 0ull;
            acc[q][i][1] = 0ull;
        }

    const int w0 = 2 * lane;
    const char* coefBase = reinterpret_cast<const char*>(sCoef) + ig * 4 * 4 * 8;

    // Prologue: load e-tile for first rotated j
    const int j0 = (2 * ig) & 15;
    const ull* base0 = sCS + j0 * 4 * TW + w0;
    ulonglong2 e0 = *reinterpret_cast<const ulonglong2*>(base0 + 0 * TW);
    ulonglong2 e1 = *reinterpret_cast<const ulonglong2*>(base0 + 1 * TW);
    ulonglong2 e2 = *reinterpret_cast<const ulonglong2*>(base0 + 2 * TW);
    ulonglong2 e3 = *reinterpret_cast<const ulonglong2*>(base0 + 3 * TW);

    #pragma unroll 1
    for (int jx = 0; jx < IC; ++jx) {
        const int j  = (jx + 2 * ig) & 15;       // current (already in e)
        const int jn = (jx + 1 + 2 * ig) & 15;   // next

        // Prefetch next j's tile (dead final iteration re-reads j0 harmlessly)
        const ull* basen = sCS + (jx < IC - 1 ? jn : j0) * 4 * TW + w0;
        ulonglong2 f0 = *reinterpret_cast<const ulonglong2*>(basen + 0 * TW);
        ulonglong2 f1 = *reinterpret_cast<const ulonglong2*>(basen + 1 * TW);
        ulonglong2 f2 = *reinterpret_cast<const ulonglong2*>(basen + 2 * TW);
        ulonglong2 f3 = *reinterpret_cast<const ulonglong2*>(basen + 3 * TW);

        const char* cfb = coefBase + (size_t)j * OC * 32;
        #pragma unroll
        for (int i = 0; i < 4; ++i) {
            ulonglong2 p01 = *reinterpret_cast<const ulonglong2*>(cfb + i * 32);
            ull c2v = *reinterpret_cast<const ull*>(cfb + i * 32 + 16);
            ffma2(acc[0][i][0], e0.x, p01.x);
            ffma2(acc[0][i][0], e1.x, p01.y);
            ffma2(acc[0][i][0], e2.x, c2v);
            ffma2(acc[0][i][1], e1.x, p01.x);
            ffma2(acc[0][i][1], e2.x, p01.y);
            ffma2(acc[0][i][1], e3.x, c2v);
            ffma2(acc[1][i][0], e0.y, p01.x);
            ffma2(acc[1][i][0], e1.y, p01.y);
            ffma2(acc[1][i][0], e2.y, c2v);
            ffma2(acc[1][i][1], e1.y, p01.x);
            ffma2(acc[1][i][1], e2.y, p01.y);
            ffma2(acc[1][i][1], e3.y, c2v);
        }

        e0 = f0; e1 = f1; e2 = f2; e3 = f3;
    }

    // Epilogue: out = (lo + hi) / 3, STG.64
    #pragma unroll
    for (int i = 0; i < 4; ++i) {
        const int ch = ig * 4 + i;
        float* op = out + ((size_t)(n * OC + ch) * H + h0) * W + tw * TW + w0;
        #pragma unroll
        for (int r = 0; r < 2; ++r) {
            ull ax = acc[0][i][r];
            ull ay = acc[1][i][r];
            float2 o;
            o.x = (__uint_as_float((unsigned)(ax & 0xffffffffu)) +
                   __uint_as_float((unsigned)(ax >> 32))) * (1.0f / 3.0f);
            o.y = (__uint_as_float((unsigned)(ay & 0xffffffffu)) +
                   __uint_as_float((unsigned)(ay >> 32))) * (1.0f / 3.0f);
            *reinterpret_cast<float2*>(op + (size_t)r * W) = o;
        }
    }
}

extern "C" void kernel_launch(void* const* d_in, const int* in_sizes, int n_in,
                              void* d_out, int out_size) {
    const float* x     = (const float*)d_in[0];   // (8,16,128,128) f32
    const float* theta = (const float*)d_in[1];   // (1536,3) f32
    float* out = (float*)d_out;                   // (8,32,128,128) f32

    prep_kernel<<<8 + CS_BLOCKS, 256>>>(x, theta);

    dim3 grid(W / TW, H / TH, NB);                // 1024 CTAs
    contract_kernel<<<grid, 256>>>(out);
}

// round 14
// speedup vs baseline: 1.1504x; 1.1504x over previous
#include <cuda_runtime.h>

// Fixed problem shape
#define NB 8
#define IC 16
#define OC 32
#define H  128
#define W  128
#define HP 130
#define TH 2      // output rows per CTA
#define TW 64     // output cols per CTA

typedef unsigned long long ull;

// Packed coefficient table: [j][i][k] (k tight, 3 per i) = (cos th, -sin th)
// 16*32*3 ull = 12 KB
__device__ ull g_coef[IC * OC * 3];

// Packed (cos S, sin S): [n*IC][HP][W], 17 MB
__device__ ull g_cs[NB * IC * HP * W];

__device__ __forceinline__ void ffma2(ull& d, ull a, ull b) {
    asm("fma.rn.f32x2 %0, %1, %2, %0;" : "+l"(d) : "l"(a), "l"(b));
}

__device__ __forceinline__ ull pack2(float lo, float hi) {
    return (ull)__float_as_uint(lo) | ((ull)__float_as_uint(hi) << 32);
}

// ---------------- Kernel 1: coef + cs tensor, division-free ----------------
// grid (65, 128): blockIdx.y = nj, blockIdx.x covers HP*W/256 = 65 blocks.
// Blocks (x<8, y==0) additionally write the coef table (k-padded indexing).
__global__ __launch_bounds__(256)
void prep_kernel(const float* __restrict__ x, const float* __restrict__ theta) {
    const int tid = threadIdx.x;

    if (blockIdx.y == 0 && blockIdx.x < 8) {
        int t = blockIdx.x * 256 + tid;          // < 2048 (k padded to 4)
        int j = t >> 7;
        int i = (t >> 2) & 31;
        int k = t & 3;
        if (k < 3) {
            float s, c;
            sincosf(theta[(i * j) * 3 + k], &s, &c);
            g_coef[j * 96 + i * 3 + k] = pack2(c, -s);
        }
    }

    // cs part: q in [0, HP*W), hp = q>>7, w = q&127 (W = 128)
    const int nj   = blockIdx.y;
    const int q    = blockIdx.x * 256 + tid;     // < 16640 always
    const int w    = q & 127;
    const int hp   = q >> 7;
    const int lane = tid & 31;

    ull outv;
    int gr = hp - 1;
    if ((unsigned)gr < (unsigned)H) {
        const float* xr = x + ((size_t)nj * H + gr) * W;
        float v  = xr[w];
        float vm = __shfl_up_sync(0xffffffffu, v, 1);
        if (lane == 0)  vm = (w > 0)   ? xr[w - 1] : 0.f;
        float vp = __shfl_down_sync(0xffffffffu, v, 1);
        if (lane == 31) vp = (w < 127) ? xr[w + 1] : 0.f;
        float S = vm + v + vp;
        float s, c;
        __sincosf(S, &s, &c);
        outv = pack2(c, s);
    } else {
        outv = pack2(1.f, 0.f);   // S = 0 on pad rows
    }
    g_cs[(size_t)nj * (HP * W) + q] = outv;
}

// ---------------- Kernel 2: contraction, 2x64 tile, occ 3 (R11 base) -------
// grid (2, 64, 8) = 1024 CTAs. 8 warps; warp ig owns channels 4*ig..4*ig+3.
// Thread owns cols {2*lane, 2*lane+1}, rows {h0, h0+1}; CS rows h0..h0+3.
// Coefficients packed 96B per (j, ig): 6 LDS.128 per j (vs 8 loads before).
__global__ __launch_bounds__(256, 3)
void contract_kernel(float* __restrict__ out) {
    __shared__ __align__(16) ull sCS[IC * (TH + 2) * TW];  // 32 KB
    __shared__ __align__(16) ull sCoef[IC * OC * 3];       // 12 KB

    const int tid  = threadIdx.x;
    const int lane = tid & 31;
    const int ig   = tid >> 5;
    const int tw   = blockIdx.x;
    const int h0   = blockIdx.y * TH;
    const int n    = blockIdx.z;

    // Stage coef table: 768 float4, 3 per thread
    {
        const float4* src = reinterpret_cast<const float4*>(g_coef);
        float4* dst = reinterpret_cast<float4*>(sCoef);
        #pragma unroll
        for (int r = 0; r < 3; ++r)
            dst[tid + 256 * r] = src[tid + 256 * r];
    }

    // Stage CS slab: 16 j x 4 rows x 64 cols = 2048 ulonglong2 (8/thread)
    {
        const ull* gsrc = g_cs + ((size_t)n * IC * HP + h0) * W + tw * TW;
        #pragma unroll
        for (int it = 0; it < 8; ++it) {
            int q   = it * 256 + tid;     // 0..2047
            int c2  = q & 31;             // ulonglong2 within row
            int row = q >> 5;             // 0..63
            int r   = row & 3;
            int j   = row >> 2;
            ulonglong2 v = *reinterpret_cast<const ulonglong2*>(
                gsrc + ((size_t)j * HP + r) * W + 2 * c2);
            *reinterpret_cast<ulonglong2*>(sCS + (j * 4 + r) * TW + 2 * c2) = v;
        }
    }
    __syncthreads();   // the only barrier

    // acc[q][i][r]: q = col-in-pair, i = channel, r = output row
    ull acc[2][4][2];
    #pragma unroll
    for (int q = 0; q < 2; ++q)
        #pragma unroll
        for (int i = 0; i < 4; ++i) {
            acc[q][i][0] = 0ull;
            acc[q][i][1] = 0ull;
        }

    const int w0 = 2 * lane;
    // warp's coef base: 96 bytes per ig group within each j's 768-byte block
    const char* coefBase = reinterpret_cast<const char*>(sCoef) + ig * 96;

    #pragma unroll 1
    for (int jx = 0; jx < IC; ++jx) {
        const int j = (jx + 2 * ig) & 15;        // per-warp rotation

        const ull* base = sCS + j * 4 * TW + w0;
        ulonglong2 e0 = *reinterpret_cast<const ulonglong2*>(base + 0 * TW);
        ulonglong2 e1 = *reinterpret_cast<const ulonglong2*>(base + 1 * TW);
        ulonglong2 e2 = *reinterpret_cast<const ulonglong2*>(base + 2 * TW);
        ulonglong2 e3 = *reinterpret_cast<const ulonglong2*>(base + 3 * TW);

        // 12 coef pairs for this (j, ig): 6 LDS.128 (warp-broadcast)
        const char* cfb = coefBase + j * 768;
        ulonglong2 p0 = *reinterpret_cast<const ulonglong2*>(cfb + 0);
        ulonglong2 p1 = *reinterpret_cast<const ulonglong2*>(cfb + 16);
        ulonglong2 p2 = *reinterpret_cast<const ulonglong2*>(cfb + 32);
        ulonglong2 p3 = *reinterpret_cast<const ulonglong2*>(cfb + 48);
        ulonglong2 p4 = *reinterpret_cast<const ulonglong2*>(cfb + 64);
        ulonglong2 p5 = *reinterpret_cast<const ulonglong2*>(cfb + 80);

        // i -> (c0, c1, c2) mapping over the packed pairs
        ull C0[4] = { p0.x, p1.y, p3.x, p4.y };
        ull C1[4] = { p0.y, p2.x, p3.y, p5.x };
        ull C2[4] = { p1.x, p2.y, p4.x, p5.y };

        #pragma unroll
        for (int i = 0; i < 4; ++i) {
            ffma2(acc[0][i][0], e0.x, C0[i]);
            ffma2(acc[0][i][0], e1.x, C1[i]);
            ffma2(acc[0][i][0], e2.x, C2[i]);
            ffma2(acc[0][i][1], e1.x, C0[i]);
            ffma2(acc[0][i][1], e2.x, C1[i]);
            ffma2(acc[0][i][1], e3.x, C2[i]);
            ffma2(acc[1][i][0], e0.y, C0[i]);
            ffma2(acc[1][i][0], e1.y, C1[i]);
            ffma2(acc[1][i][0], e2.y, C2[i]);
            ffma2(acc[1][i][1], e1.y, C0[i]);
            ffma2(acc[1][i][1], e2.y, C1[i]);
            ffma2(acc[1][i][1], e3.y, C2[i]);
        }
    }

    // Epilogue: out = (lo + hi) / 3, STG.64
    #pragma unroll
    for (int i = 0; i < 4; ++i) {
        const int ch = ig * 4 + i;
        float* op = out + ((size_t)(n * OC + ch) * H + h0) * W + tw * TW + w0;
        #pragma unroll
        for (int r = 0; r < 2; ++r) {
            ull ax = acc[0][i][r];
            ull ay = acc[1][i][r];
            float2 o;
            o.x = (__uint_as_float((unsigned)(ax & 0xffffffffu)) +
                   __uint_as_float((unsigned)(ax >> 32))) * (1.0f / 3.0f);
            o.y = (__uint_as_float((unsigned)(ay & 0xffffffffu)) +
                   __uint_as_float((unsigned)(ay >> 32))) * (1.0f / 3.0f);
            *reinterpret_cast<float2*>(op + (size_t)r * W) = o;
        }
    }
}

extern "C" void kernel_launch(void* const* d_in, const int* in_sizes, int n_in,
                              void* d_out, int out_size) {
    const float* x     = (const float*)d_in[0];   // (8,16,128,128) f32
    const float* theta = (const float*)d_in[1];   // (1536,3) f32
    float* out = (float*)d_out;                   // (8,32,128,128) f32

    dim3 pgrid(HP * W / 256, NB * IC);            // (65, 128)
    prep_kernel<<<pgrid, 256>>>(x, theta);

    dim3 grid(W / TW, H / TH, NB);                // 1024 CTAs
    contract_kernel<<<grid, 256>>>(out);
}